// round 14
// baseline (speedup 1.0000x reference)
#include <cuda_runtime.h>
#include <math.h>

#define THREADS 256
#define NBLOCKS 256
#define T 128

typedef unsigned long long F2;

__device__ __forceinline__ F2 pk2(float lo, float hi) {
    F2 r; asm("mov.b64 %0,{%1,%2};" : "=l"(r) : "f"(lo), "f"(hi)); return r;
}
__device__ __forceinline__ void upk2(F2 v, float& lo, float& hi) {
    asm("mov.b64 {%0,%1},%2;" : "=f"(lo), "=f"(hi) : "l"(v));
}
__device__ __forceinline__ F2 fma2(F2 a, F2 b, F2 c) {
    F2 d; asm("fma.rn.f32x2 %0,%1,%2,%3;" : "=l"(d) : "l"(a), "l"(b), "l"(c)); return d;
}
__device__ __forceinline__ F2 add2(F2 a, F2 b) {
    F2 d; asm("add.rn.f32x2 %0,%1,%2;" : "=l"(d) : "l"(a), "l"(b)); return d;
}
__device__ __forceinline__ F2 dup2(float w) { return pk2(w, w); }

__device__ __forceinline__ float tanh_fast(float x) {
    float e = __expf(2.0f * x);
    return 1.0f - __fdividef(2.0f, e + 1.0f);
}

// ---- smem float offsets ----
#define OFF_W1   0        // 2048
#define OFF_W2   2048     // 4096
#define OFF_HW   6144     // 2048  HW[j][c] pad32
#define OFF_E1W  8192     // 64
#define OFF_E1B  8256     // 64
#define OFF_E2T  8320     // 544 Enc2T[d][i] 8x68
#define OFF_E2B  8864     // 8
#define OFF_B1   8872     // 64
#define OFF_B2   8936     // 64
#define OFF_INIT 9000     // 32
#define OFF_HB   9032     // 32
#define OFF_RES  9064     // 64 [seq16][slot4]
#define W_TOT    9128

// per-quad shared (float offsets): 8 seqs = 4 sp-pairs
#define Q_TMP   0         // F2 [sp4][32]         256 f
#define Q_TH    256       // F2 [s4][sp4][32]     1024 f
#define Q_PART  1280      // F2 [c4][sp4][32]     1024 f
#define Q_E     2304      // float [s4][seq8][8]  256 f
#define Q_X     2560      // float [5][8] pad     48 f
#define QUAD_SZ 2608

// per-warp private
#define P_H1 0            // F2 [q4][64]  512 f
#define P_H2 512          // 512 f
#define P_HD 1024         // F2 [q4][32]  256 f
#define WARP_SZ 1280

#define SMEM_FLOATS (W_TOT + 2*QUAD_SZ + 8*WARP_SZ)   // 24584 f ≈ 98.3 KB

__global__ void __launch_bounds__(THREADS, 2) wfa_kernel(
    const float* __restrict__ x,
    const float* __restrict__ enc1_w, const float* __restrict__ enc1_b,
    const float* __restrict__ enc2_w, const float* __restrict__ enc2_b,
    const float* __restrict__ A_g,
    const float* __restrict__ init_w,
    const float* __restrict__ n1w, const float* __restrict__ n1b,
    const float* __restrict__ n2w, const float* __restrict__ n2b,
    const float* __restrict__ mu_w, const float* __restrict__ mu_b,
    const float* __restrict__ sg_w, const float* __restrict__ sg_b,
    const float* __restrict__ al_w, const float* __restrict__ al_b,
    float* __restrict__ out)
{
    extern __shared__ float sm[];
    const int tid = threadIdx.x;

    // ---- stage weights ----
    for (int i = tid; i < 2048; i += THREADS) sm[OFF_W1 + i] = n1w[i];
    for (int i = tid; i < 4096; i += THREADS) sm[OFF_W2 + i] = n2w[i];
    for (int i = tid; i < 2048; i += THREADS) {
        int j = i >> 5, c = i & 31;
        float v = 0.0f;
        if (c < 10)      v = mu_w[j * 10 + c];
        else if (c < 20) v = sg_w[j * 10 + (c - 10)];
        else if (c < 30) v = al_w[j * 10 + (c - 20)];
        sm[OFF_HW + i] = v;
    }
    for (int i = tid; i < 544; i += THREADS) {
        int d = i / 68, ii = i % 68;
        sm[OFF_E2T + i] = (ii < 64) ? enc2_w[ii * 8 + d] : 0.0f;
    }
    if (tid < 64) {
        sm[OFF_E1W + tid] = enc1_w[tid];
        sm[OFF_E1B + tid] = enc1_b[tid];
        sm[OFF_B1 + tid]  = n1b[tid];
        sm[OFF_B2 + tid]  = n2b[tid];
    }
    if (tid < 8)  sm[OFF_E2B + tid]  = enc2_b[tid];
    if (tid < 32) sm[OFF_INIT + tid] = init_w[tid];
    if (tid < 32) {
        int c = tid; float v = 0.0f;
        if (c < 10)      v = mu_b[c];
        else if (c < 20) v = sg_b[c - 10];
        else if (c < 30) v = al_b[c - 20];
        sm[OFF_HB + c] = v;
    }
    __syncthreads();

    const unsigned FULL = 0xffffffffu;
    const int wid  = tid >> 5;
    const int l    = tid & 31;
    const int quad = wid >> 2;         // 0..1
    const int p    = wid & 3;          // warp within quad, owns sp = p
    const int barid = 1 + quad;

    float* qm = sm + W_TOT + quad * QUAD_SZ;
    F2* tmpS  = (F2*)(qm + Q_TMP);     // [sp*32 + j]
    F2* thS   = (F2*)(qm + Q_TH);      // [(s*4+sp)*32 + j]
    F2* partS = (F2*)(qm + Q_PART);    // [(c*4+sp)*32 + l]
    float* eSf = qm + Q_E;             // [s*64 + seq*8 + d]
    float* xSf = qm + Q_X;             // [slot*8 + seq]

    float* wm = sm + W_TOT + 2 * QUAD_SZ + wid * WARP_SZ;
    F2* h1S = (F2*)(wm + P_H1);
    F2* h2S = (F2*)(wm + P_H2);
    F2* hdS = (F2*)(wm + P_HD);
    float* hdf = (float*)hdS;

    // ---- register caches ----
    // A octet, d-packed: Areg2[k][dp] = (A[8p+k][2dp][l], A[8p+k][2dp+1][l])
    F2 Areg2[8][4];
    #pragma unroll
    for (int k = 0; k < 8; k++) {
        const int i = p * 8 + k;
        #pragma unroll
        for (int dp = 0; dp < 4; dp++) {
            float a0 = __ldg(&A_g[i * 256 + (2 * dp) * 32 + l]);
            float a1 = __ldg(&A_g[i * 256 + (2 * dp + 1) * 32 + l]);
            Areg2[k][dp] = pk2(a0, a1);
        }
    }
    const F2 B1a = dup2(sm[OFF_B1 + 2 * l]);
    const F2 B1b = dup2(sm[OFF_B1 + 2 * l + 1]);
    const F2 B2a = dup2(sm[OFF_B2 + 2 * l]);
    const F2 B2b = dup2(sm[OFF_B2 + 2 * l + 1]);
    const F2 HBd = dup2(sm[OFF_HB + l]);

    // encoder role: seq = l&1, d = (l>>1)&7, step-half = l>>4
    const int e_sq = l & 1;
    const int e_d  = (l >> 1) & 7;
    const int e_h  = l >> 4;           // 0: steps 0,1   1: steps 2,3
    const float e2b = sm[OFF_E2B + e_d];

    // mixture role: seq = l>>2 (0..7), k-split over 4 lanes (3/3/2/2)
    const int seqm  = l >> 2;
    const int kpart = l & 3;
    const int kstart = (kpart < 2) ? kpart * 3 : 2 + kpart * 2;  // 0,3,6,8
    const int kcount = (kpart < 2) ? 3 : 2;
    const int hd_base = (seqm >> 1) * 64 + (seqm & 1);

    const int n0 = blockIdx.x * 16 + quad * 8;
    const float HALF_LOG2PI = 0.9189385332046727f;

    // ---- init state: warp p owns sp = p (seqs 2p, 2p+1) ----
    F2 tmpP = dup2(sm[OFF_INIT + l]);
    tmpS[p * 32 + l] = tmpP;

    float res = 0.0f;
    float xlast = 0.0f;

    #pragma unroll 1
    for (int it = 0; it < 32; it++) {
        asm volatile("bar.sync %0, 128;" :: "r"(barid) : "memory");   // A

        // ---- stage x for window (warp-local: seqs 2p, 2p+1) ----
        if (l < 2) xSf[2 * p + l] = xlast;
        if (l < 8) {
            int s = l >> 1, sq = l & 1;
            xSf[(s + 1) * 8 + 2 * p + sq] =
                __ldg(&x[(size_t)(n0 + 2 * p + sq) * T + it * 4 + s]);
        }
        __syncwarp();
        if (l < 2) xlast = xSf[4 * 8 + 2 * p + l];

        // ---- encoder: lane does 2 steps for (seq=e_sq, d=e_d) ----
        {
            const int sA = 2 * e_h, sB = 2 * e_h + 1;
            const float xA = xSf[sA * 8 + 2 * p + e_sq];
            const float xB = xSf[sB * 8 + 2 * p + e_sq];
            float accA = 0.f, accB = 0.f;
            const float* Et = sm + OFF_E2T + e_d * 68;
            #pragma unroll 4
            for (int i = 0; i < 64; i += 4) {
                float4 wv = *(const float4*)&sm[OFF_E1W + i];
                float4 bv = *(const float4*)&sm[OFF_E1B + i];
                float4 tv = *(const float4*)&Et[i];
                float h;
                h = fmaxf(fmaf(xA, wv.x, bv.x), 0.f); accA = fmaf(h, tv.x, accA);
                h = fmaxf(fmaf(xB, wv.x, bv.x), 0.f); accB = fmaf(h, tv.x, accB);
                h = fmaxf(fmaf(xA, wv.y, bv.y), 0.f); accA = fmaf(h, tv.y, accA);
                h = fmaxf(fmaf(xB, wv.y, bv.y), 0.f); accB = fmaf(h, tv.y, accB);
                h = fmaxf(fmaf(xA, wv.z, bv.z), 0.f); accA = fmaf(h, tv.z, accA);
                h = fmaxf(fmaf(xB, wv.z, bv.z), 0.f); accB = fmaf(h, tv.z, accB);
                h = fmaxf(fmaf(xA, wv.w, bv.w), 0.f); accA = fmaf(h, tv.w, accA);
                h = fmaxf(fmaf(xB, wv.w, bv.w), 0.f); accB = fmaf(h, tv.w, accB);
            }
            const int eb = (2 * p + e_sq) * 8 + e_d;
            eSf[sA * 64 + eb] = tanh_fast(accA + e2b);
            eSf[sB * 64 + eb] = tanh_fast(accB + e2b);
        }
        asm volatile("bar.sync %0, 128;" :: "r"(barid) : "memory");   // C

        // ---- 4 sequential micro-steps ----
        #pragma unroll 1
        for (int s = 0; s < 4; s++) {
            if (it * 4 + s > 0) {
                // i-partial (chunk 8p..8p+7), e-combined, for all 4 sp
                #pragma unroll 2
                for (int sp = 0; sp < 4; sp++) {
                    const F2* tr = &tmpS[sp * 32 + 8 * p];
                    ulonglong2 t0 = *(const ulonglong2*)&tr[0];
                    ulonglong2 t1 = *(const ulonglong2*)&tr[2];
                    ulonglong2 t2 = *(const ulonglong2*)&tr[4];
                    ulonglong2 t3 = *(const ulonglong2*)&tr[6];
                    F2 tF[8] = {t0.x,t0.y,t1.x,t1.y,t2.x,t2.y,t3.x,t3.y};
                    F2 ua0=0,ua1=0,ua2=0,ua3=0,ub0=0,ub1=0,ub2=0,ub3=0;
                    #pragma unroll
                    for (int k = 0; k < 8; k++) {
                        float ta, tb; upk2(tF[k], ta, tb);
                        F2 da = dup2(ta), db = dup2(tb);
                        ua0 = fma2(da, Areg2[k][0], ua0);
                        ua1 = fma2(da, Areg2[k][1], ua1);
                        ua2 = fma2(da, Areg2[k][2], ua2);
                        ua3 = fma2(da, Areg2[k][3], ua3);
                        ub0 = fma2(db, Areg2[k][0], ub0);
                        ub1 = fma2(db, Areg2[k][1], ub1);
                        ub2 = fma2(db, Areg2[k][2], ub2);
                        ub3 = fma2(db, Areg2[k][3], ub3);
                    }
                    const float* ea = &eSf[s * 64 + (2 * sp) * 8];
                    ulonglong2 ev0 = *(const ulonglong2*)&ea[0];
                    ulonglong2 ev1 = *(const ulonglong2*)&ea[4];
                    ulonglong2 fv0 = *(const ulonglong2*)&ea[8];
                    ulonglong2 fv1 = *(const ulonglong2*)&ea[12];
                    F2 wa = 0, wb = 0;
                    wa = fma2(ev0.x, ua0, wa); wa = fma2(ev0.y, ua1, wa);
                    wa = fma2(ev1.x, ua2, wa); wa = fma2(ev1.y, ua3, wa);
                    wb = fma2(fv0.x, ub0, wb); wb = fma2(fv0.y, ub1, wb);
                    wb = fma2(fv1.x, ub2, wb); wb = fma2(fv1.y, ub3, wb);
                    float wa0, wa1, wb0, wb1;
                    upk2(wa, wa0, wa1); upk2(wb, wb0, wb1);
                    partS[(p * 4 + sp) * 32 + l] = pk2(wa0 + wa1, wb0 + wb1);
                }
                asm volatile("bar.sync %0, 128;" :: "r"(barid) : "memory");  // D
                // combine own sp = p over 4 chunks
                {
                    F2 v0 = add2(partS[(0 * 4 + p) * 32 + l],
                                 partS[(1 * 4 + p) * 32 + l]);
                    F2 v1 = add2(partS[(2 * 4 + p) * 32 + l],
                                 partS[(3 * 4 + p) * 32 + l]);
                    tmpP = add2(v0, v1);
                }
            }
            // publish tmp + tanh(tmp) for sp = p
            tmpS[p * 32 + l] = tmpP;
            {
                float ta, tb; upk2(tmpP, ta, tb);
                thS[(s * 4 + p) * 32 + l] = pk2(tanh_fast(ta), tanh_fast(tb));
            }
            asm volatile("bar.sync %0, 128;" :: "r"(barid) : "memory");      // E
        }

        // ===== phi: warp p processes step p's 8 rows (4 q-pairs) =====
        const F2* thB = thS + p * 128;

        // --- W1: 32 -> 64, lane owns o = 2l, 2l+1 ---
        {
            F2 hA[4], hB[4];
            #pragma unroll
            for (int q = 0; q < 4; q++) { hA[q] = B1a; hB[q] = B1b; }
            #pragma unroll 2
            for (int ii = 0; ii < 16; ii++) {
                const int i = ii * 2;
                float2 w0 = *(const float2*)&sm[OFF_W1 + i * 64 + 2 * l];
                float2 w1 = *(const float2*)&sm[OFF_W1 + (i + 1) * 64 + 2 * l];
                F2 w00 = dup2(w0.x), w01 = dup2(w0.y), w10 = dup2(w1.x), w11 = dup2(w1.y);
                #pragma unroll
                for (int q = 0; q < 4; q++) {
                    ulonglong2 v = *(const ulonglong2*)&thB[q * 32 + i];
                    hA[q] = fma2(v.x, w00, hA[q]);
                    hB[q] = fma2(v.x, w01, hB[q]);
                    hA[q] = fma2(v.y, w10, hA[q]);
                    hB[q] = fma2(v.y, w11, hB[q]);
                }
            }
            #pragma unroll
            for (int q = 0; q < 4; q++) {
                float a, b;
                upk2(hA[q], a, b); F2 p0 = pk2(fmaxf(a, 0.f), fmaxf(b, 0.f));
                upk2(hB[q], a, b); F2 p1 = pk2(fmaxf(a, 0.f), fmaxf(b, 0.f));
                ulonglong2 st; st.x = p0; st.y = p1;
                *(ulonglong2*)&h1S[q * 64 + 2 * l] = st;
            }
        }
        __syncwarp();

        // --- W2: 64 -> 64 ---
        {
            F2 hA[4], hB[4];
            #pragma unroll
            for (int q = 0; q < 4; q++) { hA[q] = B2a; hB[q] = B2b; }
            #pragma unroll 2
            for (int kk = 0; kk < 32; kk++) {
                const int k = kk * 2;
                float2 w0 = *(const float2*)&sm[OFF_W2 + k * 64 + 2 * l];
                float2 w1 = *(const float2*)&sm[OFF_W2 + (k + 1) * 64 + 2 * l];
                F2 w00 = dup2(w0.x), w01 = dup2(w0.y), w10 = dup2(w1.x), w11 = dup2(w1.y);
                #pragma unroll
                for (int q = 0; q < 4; q++) {
                    ulonglong2 v = *(const ulonglong2*)&h1S[q * 64 + k];
                    hA[q] = fma2(v.x, w00, hA[q]);
                    hB[q] = fma2(v.x, w01, hB[q]);
                    hA[q] = fma2(v.y, w10, hA[q]);
                    hB[q] = fma2(v.y, w11, hB[q]);
                }
            }
            #pragma unroll
            for (int q = 0; q < 4; q++) {
                float a, b;
                upk2(hA[q], a, b); F2 p0 = pk2(fmaxf(a, 0.f), fmaxf(b, 0.f));
                upk2(hB[q], a, b); F2 p1 = pk2(fmaxf(a, 0.f), fmaxf(b, 0.f));
                ulonglong2 st; st.x = p0; st.y = p1;
                *(ulonglong2*)&h2S[q * 64 + 2 * l] = st;
            }
        }
        __syncwarp();

        // --- heads: 64 -> 30, lane owns c = l, weights via distributed LDS.32 ---
        {
            F2 hd[4];
            #pragma unroll
            for (int q = 0; q < 4; q++) hd[q] = HBd;
            #pragma unroll 2
            for (int jj = 0; jj < 32; jj++) {
                const int j = jj * 2;
                F2 w0 = dup2(sm[OFF_HW + j * 32 + l]);
                F2 w1 = dup2(sm[OFF_HW + (j + 1) * 32 + l]);
                #pragma unroll
                for (int q = 0; q < 4; q++) {
                    ulonglong2 v = *(const ulonglong2*)&h2S[q * 64 + j];
                    hd[q] = fma2(v.x, w0, hd[q]);
                    hd[q] = fma2(v.y, w1, hd[q]);
                }
            }
            #pragma unroll
            for (int q = 0; q < 4; q++) hdS[q * 32 + l] = hd[q];
        }
        __syncwarp();

        // ===== mixture: step p, 8 seqs, 4 lanes/seq (k-split 3/3/2/2) =====
        {
            const float xt_m = xSf[(p + 1) * 8 + seqm];
            float ck[3], ak[3];
            float cmax = -1e30f, amax = -1e30f;
            #pragma unroll
            for (int kk = 0; kk < 3; kk++) {
                float cc = -1e30f, al = -1e30f;
                if (kk < kcount) {
                    const int k = kstart + kk;
                    float mu = hdf[hd_base + k * 2];
                    float sg = hdf[hd_base + (10 + k) * 2];
                    al       = hdf[hd_base + (20 + k) * 2];
                    float z = (xt_m - mu) * __expf(-sg);
                    cc = fmaf(z, -0.5f * z, al - sg) - HALF_LOG2PI;
                }
                ck[kk] = cc; ak[kk] = al;
                cmax = fmaxf(cmax, cc); amax = fmaxf(amax, al);
            }
            cmax = fmaxf(cmax, __shfl_xor_sync(FULL, cmax, 1));
            cmax = fmaxf(cmax, __shfl_xor_sync(FULL, cmax, 2));
            amax = fmaxf(amax, __shfl_xor_sync(FULL, amax, 1));
            amax = fmaxf(amax, __shfl_xor_sync(FULL, amax, 2));
            float sc = 0.0f, sa = 0.0f;
            #pragma unroll
            for (int kk = 0; kk < 3; kk++) {
                if (kk < kcount) {
                    sc += __expf(ck[kk] - cmax);
                    sa += __expf(ak[kk] - amax);
                }
            }
            sc += __shfl_xor_sync(FULL, sc, 1);
            sc += __shfl_xor_sync(FULL, sc, 2);
            sa += __shfl_xor_sync(FULL, sa, 1);
            sa += __shfl_xor_sync(FULL, sa, 2);
            res += (cmax + __logf(sc)) - (amax + __logf(sa));
        }
    }

    // ---- final: per-(seq, step) partials, reduce over 4 steps ----
    if (kpart == 0) sm[OFF_RES + (quad * 8 + seqm) * 4 + p] = res;
    __syncthreads();
    if (tid < 16) {
        const float* rb = sm + OFF_RES + tid * 4;
        out[blockIdx.x * 16 + tid] = expf(rb[0] + rb[1] + rb[2] + rb[3]);
    }
}

extern "C" void kernel_launch(void* const* d_in, const int* in_sizes, int n_in,
                              void* d_out, int out_size) {
    const float* x      = (const float*)d_in[0];
    const float* enc1_w = (const float*)d_in[1];
    const float* enc1_b = (const float*)d_in[2];
    const float* enc2_w = (const float*)d_in[3];
    const float* enc2_b = (const float*)d_in[4];
    const float* A      = (const float*)d_in[5];
    const float* init_w = (const float*)d_in[6];
    const float* n1w    = (const float*)d_in[7];
    const float* n1b    = (const float*)d_in[8];
    const float* n2w    = (const float*)d_in[9];
    const float* n2b    = (const float*)d_in[10];
    const float* mu_w   = (const float*)d_in[11];
    const float* mu_b   = (const float*)d_in[12];
    const float* sg_w   = (const float*)d_in[13];
    const float* sg_b   = (const float*)d_in[14];
    const float* al_w   = (const float*)d_in[15];
    const float* al_b   = (const float*)d_in[16];
    float* out = (float*)d_out;

    const int smem_bytes = SMEM_FLOATS * (int)sizeof(float);
    cudaFuncSetAttribute(wfa_kernel, cudaFuncAttributeMaxDynamicSharedMemorySize, smem_bytes);
    wfa_kernel<<<NBLOCKS, THREADS, smem_bytes>>>(
        x, enc1_w, enc1_b, enc2_w, enc2_b, A, init_w,
        n1w, n1b, n2w, n2b, mu_w, mu_b, sg_w, sg_b, al_w, al_b, out);
}

// round 15
// speedup vs baseline: 1.0569x; 1.0569x over previous
#include <cuda_runtime.h>
#include <math.h>

#define THREADS 256
#define NBLOCKS 128
#define T 128

typedef unsigned long long F2;

__device__ __forceinline__ F2 pk2(float lo, float hi) {
    F2 r; asm("mov.b64 %0,{%1,%2};" : "=l"(r) : "f"(lo), "f"(hi)); return r;
}
__device__ __forceinline__ void upk2(F2 v, float& lo, float& hi) {
    asm("mov.b64 {%0,%1},%2;" : "=f"(lo), "=f"(hi) : "l"(v));
}
__device__ __forceinline__ F2 fma2(F2 a, F2 b, F2 c) {
    F2 d; asm("fma.rn.f32x2 %0,%1,%2,%3;" : "=l"(d) : "l"(a), "l"(b), "l"(c)); return d;
}
__device__ __forceinline__ F2 add2(F2 a, F2 b) {
    F2 d; asm("add.rn.f32x2 %0,%1,%2;" : "=l"(d) : "l"(a), "l"(b)); return d;
}
__device__ __forceinline__ F2 dup2(float w) { return pk2(w, w); }

__device__ __forceinline__ float tanh_fast(float x) {
    float e = __expf(2.0f * x);
    return 1.0f - __fdividef(2.0f, e + 1.0f);
}

// ---- smem float offsets ----
#define OFF_W1   0        // 2048  W1p[ii][o][par] = W1[2ii+par][o]
#define OFF_W2   2048     // 4096  W2p[kk][o][par] = W2[2kk+par][o]
#define OFF_HW   6144     // 2048  HW[j][c] pad32
#define OFF_E1W  8192     // 64
#define OFF_E1B  8256     // 64
#define OFF_E2T  8320     // 544 Enc2T[d][i] 8x68
#define OFF_E2B  8864     // 8
#define OFF_B1   8872     // 64
#define OFF_B2   8936     // 64
#define OFF_INIT 9000     // 32
#define OFF_HB   9032     // 32
#define OFF_RES  9064     // 128
#define W_TOT    9192

// per-quad shared (float offsets)
#define Q_TMP   0         // F2 [sp8][32]        512 f
#define Q_TH    512       // F2 [s4][sp8][32]    2048 f
#define Q_PART  2560      // F2 [p4][sp8][32]    2048 f
#define Q_E     4608      // float [s4][seq16][8] 512 f
#define Q_X     5120      // float [5][16]       96 f
#define QUAD_SZ 5216

// per-warp private
#define P_H1 0            // F2 [q8][64]  1024 f
#define P_H2 1024         // 1024 f
#define P_HD 2048         // F2 [q8][32]  512 f
#define WARP_SZ 2560

#define SMEM_FLOATS (W_TOT + 2*QUAD_SZ + 8*WARP_SZ)

__global__ void __launch_bounds__(THREADS, 1) wfa_kernel(
    const float* __restrict__ x,
    const float* __restrict__ enc1_w, const float* __restrict__ enc1_b,
    const float* __restrict__ enc2_w, const float* __restrict__ enc2_b,
    const float* __restrict__ A_g,
    const float* __restrict__ init_w,
    const float* __restrict__ n1w, const float* __restrict__ n1b,
    const float* __restrict__ n2w, const float* __restrict__ n2b,
    const float* __restrict__ mu_w, const float* __restrict__ mu_b,
    const float* __restrict__ sg_w, const float* __restrict__ sg_b,
    const float* __restrict__ al_w, const float* __restrict__ al_b,
    float* __restrict__ out)
{
    extern __shared__ float sm[];
    const int tid = threadIdx.x;

    // ---- stage weights (W1/W2 packed by i-parity pairs) ----
    for (int g = tid; g < 2048; g += THREADS) {
        int ii = g >> 7, rest = g & 127, o = rest >> 1, par = rest & 1;
        sm[OFF_W1 + g] = n1w[(2 * ii + par) * 64 + o];
    }
    for (int g = tid; g < 4096; g += THREADS) {
        int kk = g >> 7, rest = g & 127, o = rest >> 1, par = rest & 1;
        sm[OFF_W2 + g] = n2w[(2 * kk + par) * 64 + o];
    }
    for (int i = tid; i < 2048; i += THREADS) {
        int j = i >> 5, c = i & 31;
        float v = 0.0f;
        if (c < 10)      v = mu_w[j * 10 + c];
        else if (c < 20) v = sg_w[j * 10 + (c - 10)];
        else if (c < 30) v = al_w[j * 10 + (c - 20)];
        sm[OFF_HW + i] = v;
    }
    for (int i = tid; i < 544; i += THREADS) {
        int d = i / 68, ii = i % 68;
        sm[OFF_E2T + i] = (ii < 64) ? enc2_w[ii * 8 + d] : 0.0f;
    }
    if (tid < 64) {
        sm[OFF_E1W + tid] = enc1_w[tid];
        sm[OFF_E1B + tid] = enc1_b[tid];
        sm[OFF_B1 + tid]  = n1b[tid];
        sm[OFF_B2 + tid]  = n2b[tid];
    }
    if (tid < 8)  sm[OFF_E2B + tid]  = enc2_b[tid];
    if (tid < 32) sm[OFF_INIT + tid] = init_w[tid];
    if (tid < 32) {
        int c = tid; float v = 0.0f;
        if (c < 10)      v = mu_b[c];
        else if (c < 20) v = sg_b[c - 10];
        else if (c < 30) v = al_b[c - 20];
        sm[OFF_HB + c] = v;
    }
    __syncthreads();

    const unsigned FULL = 0xffffffffu;
    const int wid  = tid >> 5;
    const int l    = tid & 31;
    const int quad = wid >> 2;
    const int p    = wid & 3;
    const int barid = 1 + quad;

    float* qm = sm + W_TOT + quad * QUAD_SZ;
    F2* tmpS  = (F2*)(qm + Q_TMP);     // [sp*32 + j]
    F2* thS   = (F2*)(qm + Q_TH);      // [(s*8+sp)*32 + j]
    F2* partS = (F2*)(qm + Q_PART);    // [(p*8+sp)*32 + j]
    float* eSf = qm + Q_E;             // [(s*16+seq)*8 + d]
    float* xSf = qm + Q_X;             // [slot*16 + seq]

    float* wm = sm + W_TOT + 2 * QUAD_SZ + wid * WARP_SZ;
    F2* h1S = (F2*)(wm + P_H1);
    F2* h2S = (F2*)(wm + P_H2);
    F2* hdS = (F2*)(wm + P_HD);
    float* hdf = (float*)hdS;

    // ---- register caches ----
    F2 Areg2[8][4];
    #pragma unroll
    for (int k = 0; k < 8; k++) {
        const int i = p * 8 + k;
        #pragma unroll
        for (int dp = 0; dp < 4; dp++) {
            float a0 = __ldg(&A_g[i * 256 + (2 * dp) * 32 + l]);
            float a1 = __ldg(&A_g[i * 256 + (2 * dp + 1) * 32 + l]);
            Areg2[k][dp] = pk2(a0, a1);
        }
    }
    float HWreg[64];
    #pragma unroll
    for (int j = 0; j < 64; j++) HWreg[j] = sm[OFF_HW + j * 32 + l];
    const F2 B1a = dup2(sm[OFF_B1 + 2 * l]);
    const F2 B1b = dup2(sm[OFF_B1 + 2 * l + 1]);
    const F2 B2a = dup2(sm[OFF_B2 + 2 * l]);
    const F2 B2b = dup2(sm[OFF_B2 + 2 * l + 1]);
    const F2 HBd = dup2(sm[OFF_HB + l]);

    const int e_sq = l & 3;
    const int e_d  = l >> 2;
    const float e2b = sm[OFF_E2B + e_d];

    const int r_m  = l >> 1;
    const int kb_m = (l & 1) * 5;
    const int hd_base = (r_m >> 1) * 64 + (r_m & 1);

    const int n0 = blockIdx.x * 32 + quad * 16;
    const float HALF_LOG2PI = 0.9189385332046727f;

    // ---- init state: warp p owns sp = 2p, 2p+1 ----
    F2 tmpP[2];
    {
        float iv = sm[OFF_INIT + l];
        tmpP[0] = dup2(iv); tmpP[1] = tmpP[0];
        tmpS[(2 * p) * 32 + l]     = tmpP[0];
        tmpS[(2 * p + 1) * 32 + l] = tmpP[1];
    }

    float res = 0.0f;
    float xlast = 0.0f;

    #pragma unroll 1
    for (int it = 0; it < 32; it++) {
        asm volatile("bar.sync %0, 128;" :: "r"(barid) : "memory");   // A

        // ---- stage x for window ----
        if (l < 4) xSf[4 * p + l] = xlast;
        if (l < 16) {
            int s = l >> 2, sq = l & 3;
            xSf[(s + 1) * 16 + 4 * p + sq] =
                __ldg(&x[(size_t)(n0 + 4 * p + sq) * T + it * 4 + s]);
        }
        __syncwarp();
        if (l < 4) xlast = xSf[4 * 16 + 4 * p + l];

        // ---- encoder batched over 4 steps ----
        {
            float xe0 = xSf[0 * 16 + 4 * p + e_sq];
            float xe1 = xSf[1 * 16 + 4 * p + e_sq];
            float xe2 = xSf[2 * 16 + 4 * p + e_sq];
            float xe3 = xSf[3 * 16 + 4 * p + e_sq];
            float a0 = 0.f, a1 = 0.f, a2 = 0.f, a3 = 0.f;
            const float* Et = sm + OFF_E2T + e_d * 68;
            #pragma unroll 4
            for (int i = 0; i < 64; i += 4) {
                float4 w  = *(const float4*)&sm[OFF_E1W + i];
                float4 b  = *(const float4*)&sm[OFF_E1B + i];
                float4 tv = *(const float4*)&Et[i];
                float h;
                h = fmaxf(fmaf(xe0,w.x,b.x),0.f); a0 = fmaf(h,tv.x,a0);
                h = fmaxf(fmaf(xe1,w.x,b.x),0.f); a1 = fmaf(h,tv.x,a1);
                h = fmaxf(fmaf(xe2,w.x,b.x),0.f); a2 = fmaf(h,tv.x,a2);
                h = fmaxf(fmaf(xe3,w.x,b.x),0.f); a3 = fmaf(h,tv.x,a3);
                h = fmaxf(fmaf(xe0,w.y,b.y),0.f); a0 = fmaf(h,tv.y,a0);
                h = fmaxf(fmaf(xe1,w.y,b.y),0.f); a1 = fmaf(h,tv.y,a1);
                h = fmaxf(fmaf(xe2,w.y,b.y),0.f); a2 = fmaf(h,tv.y,a2);
                h = fmaxf(fmaf(xe3,w.y,b.y),0.f); a3 = fmaf(h,tv.y,a3);
                h = fmaxf(fmaf(xe0,w.z,b.z),0.f); a0 = fmaf(h,tv.z,a0);
                h = fmaxf(fmaf(xe1,w.z,b.z),0.f); a1 = fmaf(h,tv.z,a1);
                h = fmaxf(fmaf(xe2,w.z,b.z),0.f); a2 = fmaf(h,tv.z,a2);
                h = fmaxf(fmaf(xe3,w.z,b.z),0.f); a3 = fmaf(h,tv.z,a3);
                h = fmaxf(fmaf(xe0,w.w,b.w),0.f); a0 = fmaf(h,tv.w,a0);
                h = fmaxf(fmaf(xe1,w.w,b.w),0.f); a1 = fmaf(h,tv.w,a1);
                h = fmaxf(fmaf(xe2,w.w,b.w),0.f); a2 = fmaf(h,tv.w,a2);
                h = fmaxf(fmaf(xe3,w.w,b.w),0.f); a3 = fmaf(h,tv.w,a3);
            }
            const int eb = (4 * p + e_sq) * 8 + e_d;
            eSf[0 * 128 + eb] = tanh_fast(a0 + e2b);
            eSf[1 * 128 + eb] = tanh_fast(a1 + e2b);
            eSf[2 * 128 + eb] = tanh_fast(a2 + e2b);
            eSf[3 * 128 + eb] = tanh_fast(a3 + e2b);
        }
        asm volatile("bar.sync %0, 128;" :: "r"(barid) : "memory");   // C

        // ---- 4 sequential micro-steps ----
        #pragma unroll 1
        for (int s = 0; s < 4; s++) {
            if (it * 4 + s > 0) {
                #pragma unroll 2
                for (int sp = 0; sp < 8; sp++) {
                    const F2* tr = &tmpS[sp * 32 + 8 * p];
                    ulonglong2 t0 = *(const ulonglong2*)&tr[0];
                    ulonglong2 t1 = *(const ulonglong2*)&tr[2];
                    ulonglong2 t2 = *(const ulonglong2*)&tr[4];
                    ulonglong2 t3 = *(const ulonglong2*)&tr[6];
                    F2 tF[8] = {t0.x,t0.y,t1.x,t1.y,t2.x,t2.y,t3.x,t3.y};
                    F2 ua0=0,ua1=0,ua2=0,ua3=0,ub0=0,ub1=0,ub2=0,ub3=0;
                    #pragma unroll
                    for (int k = 0; k < 8; k++) {
                        float ta, tb; upk2(tF[k], ta, tb);
                        F2 da = dup2(ta), db = dup2(tb);
                        ua0 = fma2(da, Areg2[k][0], ua0);
                        ua1 = fma2(da, Areg2[k][1], ua1);
                        ua2 = fma2(da, Areg2[k][2], ua2);
                        ua3 = fma2(da, Areg2[k][3], ua3);
                        ub0 = fma2(db, Areg2[k][0], ub0);
                        ub1 = fma2(db, Areg2[k][1], ub1);
                        ub2 = fma2(db, Areg2[k][2], ub2);
                        ub3 = fma2(db, Areg2[k][3], ub3);
                    }
                    const float* ea = &eSf[(s * 16 + 2 * sp) * 8];
                    ulonglong2 ev0 = *(const ulonglong2*)&ea[0];
                    ulonglong2 ev1 = *(const ulonglong2*)&ea[4];
                    ulonglong2 fv0 = *(const ulonglong2*)&ea[8];
                    ulonglong2 fv1 = *(const ulonglong2*)&ea[12];
                    F2 wa = 0, wb = 0;
                    wa = fma2(ev0.x, ua0, wa); wa = fma2(ev0.y, ua1, wa);
                    wa = fma2(ev1.x, ua2, wa); wa = fma2(ev1.y, ua3, wa);
                    wb = fma2(fv0.x, ub0, wb); wb = fma2(fv0.y, ub1, wb);
                    wb = fma2(fv1.x, ub2, wb); wb = fma2(fv1.y, ub3, wb);
                    float wa0, wa1, wb0, wb1;
                    upk2(wa, wa0, wa1); upk2(wb, wb0, wb1);
                    partS[(p * 8 + sp) * 32 + l] = pk2(wa0 + wa1, wb0 + wb1);
                }
                asm volatile("bar.sync %0, 128;" :: "r"(barid) : "memory");  // D
                #pragma unroll
                for (int b = 0; b < 2; b++) {
                    const int sp = 2 * p + b;
                    F2 v0 = add2(partS[(0 * 8 + sp) * 32 + l],
                                 partS[(1 * 8 + sp) * 32 + l]);
                    F2 v1 = add2(partS[(2 * 8 + sp) * 32 + l],
                                 partS[(3 * 8 + sp) * 32 + l]);
                    tmpP[b] = add2(v0, v1);
                }
            }
            // publish tmp + tanh(tmp)
            #pragma unroll
            for (int b = 0; b < 2; b++) {
                const int sp = 2 * p + b;
                tmpS[sp * 32 + l] = tmpP[b];
                float ta, tb; upk2(tmpP[b], ta, tb);
                thS[(s * 8 + sp) * 32 + l] = pk2(tanh_fast(ta), tanh_fast(tb));
            }
            asm volatile("bar.sync %0, 128;" :: "r"(barid) : "memory");      // E
        }

        // ===== phi batched: warp p processes step p's 16 rows =====
        const F2* thB = thS + p * 256;

        // --- W1: 32 -> 64, lane owns o = 2l, 2l+1 (packed pair loads) ---
        {
            F2 hA[8], hB[8];
            #pragma unroll
            for (int q = 0; q < 8; q++) { hA[q] = B1a; hB[q] = B1b; }
            #pragma unroll 2
            for (int ii = 0; ii < 16; ii++) {
                const int i = ii * 2;
                // q4 = {W1[i][2l], W1[i+1][2l], W1[i][2l+1], W1[i+1][2l+1]}
                float4 q4 = *(const float4*)&sm[OFF_W1 + ii * 128 + 4 * l];
                F2 w00 = dup2(q4.x), w10 = dup2(q4.y), w01 = dup2(q4.z), w11 = dup2(q4.w);
                #pragma unroll
                for (int q = 0; q < 8; q++) {
                    ulonglong2 v = *(const ulonglong2*)&thB[q * 32 + i];
                    hA[q] = fma2(v.x, w00, hA[q]);
                    hB[q] = fma2(v.x, w01, hB[q]);
                    hA[q] = fma2(v.y, w10, hA[q]);
                    hB[q] = fma2(v.y, w11, hB[q]);
                }
            }
            #pragma unroll
            for (int q = 0; q < 8; q++) {
                float a, b;
                upk2(hA[q], a, b); F2 p0 = pk2(fmaxf(a, 0.f), fmaxf(b, 0.f));
                upk2(hB[q], a, b); F2 p1 = pk2(fmaxf(a, 0.f), fmaxf(b, 0.f));
                ulonglong2 st; st.x = p0; st.y = p1;
                *(ulonglong2*)&h1S[q * 64 + 2 * l] = st;
            }
        }
        __syncwarp();

        // --- W2: 64 -> 64 (packed pair loads) ---
        {
            F2 hA[8], hB[8];
            #pragma unroll
            for (int q = 0; q < 8; q++) { hA[q] = B2a; hB[q] = B2b; }
            #pragma unroll 2
            for (int kk = 0; kk < 32; kk++) {
                const int k = kk * 2;
                float4 q4 = *(const float4*)&sm[OFF_W2 + kk * 128 + 4 * l];
                F2 w00 = dup2(q4.x), w10 = dup2(q4.y), w01 = dup2(q4.z), w11 = dup2(q4.w);
                #pragma unroll
                for (int q = 0; q < 8; q++) {
                    ulonglong2 v = *(const ulonglong2*)&h1S[q * 64 + k];
                    hA[q] = fma2(v.x, w00, hA[q]);
                    hB[q] = fma2(v.x, w01, hB[q]);
                    hA[q] = fma2(v.y, w10, hA[q]);
                    hB[q] = fma2(v.y, w11, hB[q]);
                }
            }
            #pragma unroll
            for (int q = 0; q < 8; q++) {
                float a, b;
                upk2(hA[q], a, b); F2 p0 = pk2(fmaxf(a, 0.f), fmaxf(b, 0.f));
                upk2(hB[q], a, b); F2 p1 = pk2(fmaxf(a, 0.f), fmaxf(b, 0.f));
                ulonglong2 st; st.x = p0; st.y = p1;
                *(ulonglong2*)&h2S[q * 64 + 2 * l] = st;
            }
        }
        __syncwarp();

        // --- heads: 64 -> 30, lane owns c = l (weights in registers) ---
        {
            F2 hd[8];
            #pragma unroll
            for (int q = 0; q < 8; q++) hd[q] = HBd;
            #pragma unroll 2
            for (int jj = 0; jj < 32; jj++) {
                const int j = jj * 2;
                F2 w0 = dup2(HWreg[j]);
                F2 w1 = dup2(HWreg[j + 1]);
                #pragma unroll
                for (int q = 0; q < 8; q++) {
                    ulonglong2 v = *(const ulonglong2*)&h2S[q * 64 + j];
                    hd[q] = fma2(v.x, w0, hd[q]);
                    hd[q] = fma2(v.y, w1, hd[q]);
                }
            }
            #pragma unroll
            for (int q = 0; q < 8; q++) hdS[q * 32 + l] = hd[q];
        }
        __syncwarp();

        // ===== mixture: step p, 16 quad-seqs, 2 lanes/seq =====
        {
            const float xt_m = xSf[(p + 1) * 16 + r_m];
            float ck[5], ak[5];
            float cmax = -1e30f, amax = -1e30f;
            #pragma unroll
            for (int k = 0; k < 5; k++) {
                float mu = hdf[hd_base + (kb_m + k) * 2];
                float sg = hdf[hd_base + (10 + kb_m + k) * 2];
                float al = hdf[hd_base + (20 + kb_m + k) * 2];
                float z = (xt_m - mu) * __expf(-sg);
                float cc = fmaf(z, -0.5f * z, al - sg) - HALF_LOG2PI;
                ck[k] = cc; ak[k] = al;
                cmax = fmaxf(cmax, cc); amax = fmaxf(amax, al);
            }
            cmax = fmaxf(cmax, __shfl_xor_sync(FULL, cmax, 1));
            amax = fmaxf(amax, __shfl_xor_sync(FULL, amax, 1));
            float sc = 0.0f, sa = 0.0f;
            #pragma unroll
            for (int k = 0; k < 5; k++) {
                sc += __expf(ck[k] - cmax);
                sa += __expf(ak[k] - amax);
            }
            sc += __shfl_xor_sync(FULL, sc, 1);
            sa += __shfl_xor_sync(FULL, sa, 1);
            res += (cmax + __logf(sc)) - (amax + __logf(sa));
        }
    }

    // ---- final cross-warp reduction ----
    if ((l & 1) == 0) sm[OFF_RES + (quad * 4 + p) * 16 + (l >> 1)] = res;
    __syncthreads();
    if (tid < 32) {
        int qd = tid >> 4, sq = tid & 15;
        const float* rb = sm + OFF_RES + qd * 64;
        out[blockIdx.x * 32 + qd * 16 + sq] =
            expf(rb[0 * 16 + sq] + rb[1 * 16 + sq] + rb[2 * 16 + sq] + rb[3 * 16 + sq]);
    }
}

extern "C" void kernel_launch(void* const* d_in, const int* in_sizes, int n_in,
                              void* d_out, int out_size) {
    const float* x      = (const float*)d_in[0];
    const float* enc1_w = (const float*)d_in[1];
    const float* enc1_b = (const float*)d_in[2];
    const float* enc2_w = (const float*)d_in[3];
    const float* enc2_b = (const float*)d_in[4];
    const float* A      = (const float*)d_in[5];
    const float* init_w = (const float*)d_in[6];
    const float* n1w    = (const float*)d_in[7];
    const float* n1b    = (const float*)d_in[8];
    const float* n2w    = (const float*)d_in[9];
    const float* n2b    = (const float*)d_in[10];
    const float* mu_w   = (const float*)d_in[11];
    const float* mu_b   = (const float*)d_in[12];
    const float* sg_w   = (const float*)d_in[13];
    const float* sg_b   = (const float*)d_in[14];
    const float* al_w   = (const float*)d_in[15];
    const float* al_b   = (const float*)d_in[16];
    float* out = (float*)d_out;

    const int smem_bytes = SMEM_FLOATS * (int)sizeof(float);
    cudaFuncSetAttribute(wfa_kernel, cudaFuncAttributeMaxDynamicSharedMemorySize, smem_bytes);
    wfa_kernel<<<NBLOCKS, THREADS, smem_bytes>>>(
        x, enc1_w, enc1_b, enc2_w, enc2_b, A, init_w,
        n1w, n1b, n2w, n2b, mu_w, mu_b, sg_w, sg_b, al_w, al_b, out);
}

// round 16
// speedup vs baseline: 1.0840x; 1.0256x over previous
#include <cuda_runtime.h>
#include <math.h>

#define THREADS 256
#define NBLOCKS 128
#define T 128

typedef unsigned long long F2;

__device__ __forceinline__ F2 pk2(float lo, float hi) {
    F2 r; asm("mov.b64 %0,{%1,%2};" : "=l"(r) : "f"(lo), "f"(hi)); return r;
}
__device__ __forceinline__ void upk2(F2 v, float& lo, float& hi) {
    asm("mov.b64 {%0,%1},%2;" : "=f"(lo), "=f"(hi) : "l"(v));
}
__device__ __forceinline__ F2 fma2(F2 a, F2 b, F2 c) {
    F2 d; asm("fma.rn.f32x2 %0,%1,%2,%3;" : "=l"(d) : "l"(a), "l"(b), "l"(c)); return d;
}
__device__ __forceinline__ F2 add2(F2 a, F2 b) {
    F2 d; asm("add.rn.f32x2 %0,%1,%2;" : "=l"(d) : "l"(a), "l"(b)); return d;
}
__device__ __forceinline__ F2 dup2(float w) { return pk2(w, w); }

// HW tanh: 1 MUFU op (vs 2 for exp+rcp route)
__device__ __forceinline__ float tanh_fast(float x) {
    float y; asm("tanh.approx.f32 %0, %1;" : "=f"(y) : "f"(x)); return y;
}

// ---- smem float offsets ----
#define OFF_W1   0        // 2048
#define OFF_W2   2048     // 4096
#define OFF_HW   6144     // 2048  HW[j][c] pad32
#define OFF_E1W  8192     // 64
#define OFF_E1B  8256     // 64
#define OFF_E2T  8320     // 544 Enc2T[d][i] 8x68
#define OFF_E2B  8864     // 8
#define OFF_B1   8872     // 64
#define OFF_B2   8936     // 64
#define OFF_INIT 9000     // 32
#define OFF_HB   9032     // 32
#define OFF_RES  9064     // 128
#define W_TOT    9192

// per-quad shared (float offsets)
#define Q_TMP   0         // F2 [sp8][32]        512 f
#define Q_TH    512       // F2 [s4][sp8][32]    2048 f
#define Q_PART  2560      // F2 [p4][sp8][32]    2048 f
#define Q_E     4608      // float [s4][seq16][8] 512 f
#define Q_X     5120      // float [5][16]       96 f
#define QUAD_SZ 5216

// per-warp private
#define P_H1 0            // F2 [q8][64]  1024 f
#define P_H2 1024         // 1024 f
#define P_HD 2048         // F2 [q8][32]  512 f
#define WARP_SZ 2560

#define SMEM_FLOATS (W_TOT + 2*QUAD_SZ + 8*WARP_SZ)

__global__ void __launch_bounds__(THREADS, 1) wfa_kernel(
    const float* __restrict__ x,
    const float* __restrict__ enc1_w, const float* __restrict__ enc1_b,
    const float* __restrict__ enc2_w, const float* __restrict__ enc2_b,
    const float* __restrict__ A_g,
    const float* __restrict__ init_w,
    const float* __restrict__ n1w, const float* __restrict__ n1b,
    const float* __restrict__ n2w, const float* __restrict__ n2b,
    const float* __restrict__ mu_w, const float* __restrict__ mu_b,
    const float* __restrict__ sg_w, const float* __restrict__ sg_b,
    const float* __restrict__ al_w, const float* __restrict__ al_b,
    float* __restrict__ out)
{
    extern __shared__ float sm[];
    const int tid = threadIdx.x;

    // ---- stage weights ----
    for (int i = tid; i < 2048; i += THREADS) sm[OFF_W1 + i] = n1w[i];
    for (int i = tid; i < 4096; i += THREADS) sm[OFF_W2 + i] = n2w[i];
    for (int i = tid; i < 2048; i += THREADS) {
        int j = i >> 5, c = i & 31;
        float v = 0.0f;
        if (c < 10)      v = mu_w[j * 10 + c];
        else if (c < 20) v = sg_w[j * 10 + (c - 10)];
        else if (c < 30) v = al_w[j * 10 + (c - 20)];
        sm[OFF_HW + i] = v;
    }
    for (int i = tid; i < 544; i += THREADS) {
        int d = i / 68, ii = i % 68;
        sm[OFF_E2T + i] = (ii < 64) ? enc2_w[ii * 8 + d] : 0.0f;
    }
    if (tid < 64) {
        sm[OFF_E1W + tid] = enc1_w[tid];
        sm[OFF_E1B + tid] = enc1_b[tid];
        sm[OFF_B1 + tid]  = n1b[tid];
        sm[OFF_B2 + tid]  = n2b[tid];
    }
    if (tid < 8)  sm[OFF_E2B + tid]  = enc2_b[tid];
    if (tid < 32) sm[OFF_INIT + tid] = init_w[tid];
    if (tid < 32) {
        int c = tid; float v = 0.0f;
        if (c < 10)      v = mu_b[c];
        else if (c < 20) v = sg_b[c - 10];
        else if (c < 30) v = al_b[c - 20];
        sm[OFF_HB + c] = v;
    }
    __syncthreads();

    const unsigned FULL = 0xffffffffu;
    const int wid  = tid >> 5;
    const int l    = tid & 31;
    const int quad = wid >> 2;
    const int p    = wid & 3;
    const int barid = 1 + quad;

    float* qm = sm + W_TOT + quad * QUAD_SZ;
    F2* tmpS  = (F2*)(qm + Q_TMP);     // [sp*32 + j]
    F2* thS   = (F2*)(qm + Q_TH);      // [(s*8+sp)*32 + j]
    F2* partS = (F2*)(qm + Q_PART);    // [(p*8+sp)*32 + j]
    float* eSf = qm + Q_E;             // [(s*16+seq)*8 + d]
    float* xSf = qm + Q_X;             // [slot*16 + seq]

    float* wm = sm + W_TOT + 2 * QUAD_SZ + wid * WARP_SZ;
    F2* h1S = (F2*)(wm + P_H1);
    F2* h2S = (F2*)(wm + P_H2);
    F2* hdS = (F2*)(wm + P_HD);
    float* hdf = (float*)hdS;

    // ---- register caches ----
    F2 Areg2[8][4];
    #pragma unroll
    for (int k = 0; k < 8; k++) {
        const int i = p * 8 + k;
        #pragma unroll
        for (int dp = 0; dp < 4; dp++) {
            float a0 = __ldg(&A_g[i * 256 + (2 * dp) * 32 + l]);
            float a1 = __ldg(&A_g[i * 256 + (2 * dp + 1) * 32 + l]);
            Areg2[k][dp] = pk2(a0, a1);
        }
    }
    float HWreg[64];
    #pragma unroll
    for (int j = 0; j < 64; j++) HWreg[j] = sm[OFF_HW + j * 32 + l];
    const F2 B1a = dup2(sm[OFF_B1 + 2 * l]);
    const F2 B1b = dup2(sm[OFF_B1 + 2 * l + 1]);
    const F2 B2a = dup2(sm[OFF_B2 + 2 * l]);
    const F2 B2b = dup2(sm[OFF_B2 + 2 * l + 1]);
    const F2 HBd = dup2(sm[OFF_HB + l]);

    const int e_sq = l & 3;
    const int e_d  = l >> 2;
    const float e2b = sm[OFF_E2B + e_d];

    const int r_m  = l >> 1;
    const int kb_m = (l & 1) * 5;
    const int hd_base = (r_m >> 1) * 64 + (r_m & 1);

    const int n0 = blockIdx.x * 32 + quad * 16;
    const float HALF_LOG2PI = 0.9189385332046727f;

    // ---- init state: warp p owns sp = 2p, 2p+1 ----
    F2 tmpP[2];
    {
        float iv = sm[OFF_INIT + l];
        tmpP[0] = dup2(iv); tmpP[1] = tmpP[0];
        tmpS[(2 * p) * 32 + l]     = tmpP[0];
        tmpS[(2 * p + 1) * 32 + l] = tmpP[1];
    }

    float res = 0.0f;
    float xlast = 0.0f;

    #pragma unroll 1
    for (int it = 0; it < 32; it++) {
        asm volatile("bar.sync %0, 128;" :: "r"(barid) : "memory");   // A

        // ---- stage x for window ----
        if (l < 4) xSf[4 * p + l] = xlast;
        if (l < 16) {
            int s = l >> 2, sq = l & 3;
            xSf[(s + 1) * 16 + 4 * p + sq] =
                __ldg(&x[(size_t)(n0 + 4 * p + sq) * T + it * 4 + s]);
        }
        __syncwarp();
        if (l < 4) xlast = xSf[4 * 16 + 4 * p + l];

        // ---- encoder batched over 4 steps ----
        {
            float xe0 = xSf[0 * 16 + 4 * p + e_sq];
            float xe1 = xSf[1 * 16 + 4 * p + e_sq];
            float xe2 = xSf[2 * 16 + 4 * p + e_sq];
            float xe3 = xSf[3 * 16 + 4 * p + e_sq];
            float a0 = 0.f, a1 = 0.f, a2 = 0.f, a3 = 0.f;
            const float* Et = sm + OFF_E2T + e_d * 68;
            #pragma unroll 4
            for (int i = 0; i < 64; i += 4) {
                float4 w  = *(const float4*)&sm[OFF_E1W + i];
                float4 b  = *(const float4*)&sm[OFF_E1B + i];
                float4 tv = *(const float4*)&Et[i];
                float h;
                h = fmaxf(fmaf(xe0,w.x,b.x),0.f); a0 = fmaf(h,tv.x,a0);
                h = fmaxf(fmaf(xe1,w.x,b.x),0.f); a1 = fmaf(h,tv.x,a1);
                h = fmaxf(fmaf(xe2,w.x,b.x),0.f); a2 = fmaf(h,tv.x,a2);
                h = fmaxf(fmaf(xe3,w.x,b.x),0.f); a3 = fmaf(h,tv.x,a3);
                h = fmaxf(fmaf(xe0,w.y,b.y),0.f); a0 = fmaf(h,tv.y,a0);
                h = fmaxf(fmaf(xe1,w.y,b.y),0.f); a1 = fmaf(h,tv.y,a1);
                h = fmaxf(fmaf(xe2,w.y,b.y),0.f); a2 = fmaf(h,tv.y,a2);
                h = fmaxf(fmaf(xe3,w.y,b.y),0.f); a3 = fmaf(h,tv.y,a3);
                h = fmaxf(fmaf(xe0,w.z,b.z),0.f); a0 = fmaf(h,tv.z,a0);
                h = fmaxf(fmaf(xe1,w.z,b.z),0.f); a1 = fmaf(h,tv.z,a1);
                h = fmaxf(fmaf(xe2,w.z,b.z),0.f); a2 = fmaf(h,tv.z,a2);
                h = fmaxf(fmaf(xe3,w.z,b.z),0.f); a3 = fmaf(h,tv.z,a3);
                h = fmaxf(fmaf(xe0,w.w,b.w),0.f); a0 = fmaf(h,tv.w,a0);
                h = fmaxf(fmaf(xe1,w.w,b.w),0.f); a1 = fmaf(h,tv.w,a1);
                h = fmaxf(fmaf(xe2,w.w,b.w),0.f); a2 = fmaf(h,tv.w,a2);
                h = fmaxf(fmaf(xe3,w.w,b.w),0.f); a3 = fmaf(h,tv.w,a3);
            }
            const int eb = (4 * p + e_sq) * 8 + e_d;
            eSf[0 * 128 + eb] = tanh_fast(a0 + e2b);
            eSf[1 * 128 + eb] = tanh_fast(a1 + e2b);
            eSf[2 * 128 + eb] = tanh_fast(a2 + e2b);
            eSf[3 * 128 + eb] = tanh_fast(a3 + e2b);
        }
        asm volatile("bar.sync %0, 128;" :: "r"(barid) : "memory");   // C

        // ---- 4 sequential micro-steps ----
        #pragma unroll 1
        for (int s = 0; s < 4; s++) {
            if (it * 4 + s > 0) {
                #pragma unroll 2
                for (int sp = 0; sp < 8; sp++) {
                    const F2* tr = &tmpS[sp * 32 + 8 * p];
                    ulonglong2 t0 = *(const ulonglong2*)&tr[0];
                    ulonglong2 t1 = *(const ulonglong2*)&tr[2];
                    ulonglong2 t2 = *(const ulonglong2*)&tr[4];
                    ulonglong2 t3 = *(const ulonglong2*)&tr[6];
                    F2 tF[8] = {t0.x,t0.y,t1.x,t1.y,t2.x,t2.y,t3.x,t3.y};
                    F2 ua0=0,ua1=0,ua2=0,ua3=0,ub0=0,ub1=0,ub2=0,ub3=0;
                    #pragma unroll
                    for (int k = 0; k < 8; k++) {
                        float ta, tb; upk2(tF[k], ta, tb);
                        F2 da = dup2(ta), db = dup2(tb);
                        ua0 = fma2(da, Areg2[k][0], ua0);
                        ua1 = fma2(da, Areg2[k][1], ua1);
                        ua2 = fma2(da, Areg2[k][2], ua2);
                        ua3 = fma2(da, Areg2[k][3], ua3);
                        ub0 = fma2(db, Areg2[k][0], ub0);
                        ub1 = fma2(db, Areg2[k][1], ub1);
                        ub2 = fma2(db, Areg2[k][2], ub2);
                        ub3 = fma2(db, Areg2[k][3], ub3);
                    }
                    const float* ea = &eSf[(s * 16 + 2 * sp) * 8];
                    ulonglong2 ev0 = *(const ulonglong2*)&ea[0];
                    ulonglong2 ev1 = *(const ulonglong2*)&ea[4];
                    ulonglong2 fv0 = *(const ulonglong2*)&ea[8];
                    ulonglong2 fv1 = *(const ulonglong2*)&ea[12];
                    F2 wa = 0, wb = 0;
                    wa = fma2(ev0.x, ua0, wa); wa = fma2(ev0.y, ua1, wa);
                    wa = fma2(ev1.x, ua2, wa); wa = fma2(ev1.y, ua3, wa);
                    wb = fma2(fv0.x, ub0, wb); wb = fma2(fv0.y, ub1, wb);
                    wb = fma2(fv1.x, ub2, wb); wb = fma2(fv1.y, ub3, wb);
                    float wa0, wa1, wb0, wb1;
                    upk2(wa, wa0, wa1); upk2(wb, wb0, wb1);
                    partS[(p * 8 + sp) * 32 + l] = pk2(wa0 + wa1, wb0 + wb1);
                }
                asm volatile("bar.sync %0, 128;" :: "r"(barid) : "memory");  // D
                #pragma unroll
                for (int b = 0; b < 2; b++) {
                    const int sp = 2 * p + b;
                    F2 v0 = add2(partS[(0 * 8 + sp) * 32 + l],
                                 partS[(1 * 8 + sp) * 32 + l]);
                    F2 v1 = add2(partS[(2 * 8 + sp) * 32 + l],
                                 partS[(3 * 8 + sp) * 32 + l]);
                    tmpP[b] = add2(v0, v1);
                }
            }
            // publish tmp + tanh(tmp)
            #pragma unroll
            for (int b = 0; b < 2; b++) {
                const int sp = 2 * p + b;
                tmpS[sp * 32 + l] = tmpP[b];
                float ta, tb; upk2(tmpP[b], ta, tb);
                thS[(s * 8 + sp) * 32 + l] = pk2(tanh_fast(ta), tanh_fast(tb));
            }
            asm volatile("bar.sync %0, 128;" :: "r"(barid) : "memory");      // E
        }

        // ===== phi batched: warp p processes step p's 16 rows =====
        const F2* thB = thS + p * 256;

        // --- W1: 32 -> 64, lane owns o = 2l, 2l+1 ---
        {
            F2 hA[8], hB[8];
            #pragma unroll
            for (int q = 0; q < 8; q++) { hA[q] = B1a; hB[q] = B1b; }
            #pragma unroll 2
            for (int ii = 0; ii < 16; ii++) {
                const int i = ii * 2;
                float2 w0 = *(const float2*)&sm[OFF_W1 + i * 64 + 2 * l];
                float2 w1 = *(const float2*)&sm[OFF_W1 + (i + 1) * 64 + 2 * l];
                F2 w00 = dup2(w0.x), w01 = dup2(w0.y), w10 = dup2(w1.x), w11 = dup2(w1.y);
                #pragma unroll
                for (int q = 0; q < 8; q++) {
                    ulonglong2 v = *(const ulonglong2*)&thB[q * 32 + i];
                    hA[q] = fma2(v.x, w00, hA[q]);
                    hB[q] = fma2(v.x, w01, hB[q]);
                    hA[q] = fma2(v.y, w10, hA[q]);
                    hB[q] = fma2(v.y, w11, hB[q]);
                }
            }
            #pragma unroll
            for (int q = 0; q < 8; q++) {
                float a, b;
                upk2(hA[q], a, b); F2 p0 = pk2(fmaxf(a, 0.f), fmaxf(b, 0.f));
                upk2(hB[q], a, b); F2 p1 = pk2(fmaxf(a, 0.f), fmaxf(b, 0.f));
                ulonglong2 st; st.x = p0; st.y = p1;
                *(ulonglong2*)&h1S[q * 64 + 2 * l] = st;
            }
        }
        __syncwarp();

        // --- W2: 64 -> 64 ---
        {
            F2 hA[8], hB[8];
            #pragma unroll
            for (int q = 0; q < 8; q++) { hA[q] = B2a; hB[q] = B2b; }
            #pragma unroll 2
            for (int kk = 0; kk < 32; kk++) {
                const int k = kk * 2;
                float2 w0 = *(const float2*)&sm[OFF_W2 + k * 64 + 2 * l];
                float2 w1 = *(const float2*)&sm[OFF_W2 + (k + 1) * 64 + 2 * l];
                F2 w00 = dup2(w0.x), w01 = dup2(w0.y), w10 = dup2(w1.x), w11 = dup2(w1.y);
                #pragma unroll
                for (int q = 0; q < 8; q++) {
                    ulonglong2 v = *(const ulonglong2*)&h1S[q * 64 + k];
                    hA[q] = fma2(v.x, w00, hA[q]);
                    hB[q] = fma2(v.x, w01, hB[q]);
                    hA[q] = fma2(v.y, w10, hA[q]);
                    hB[q] = fma2(v.y, w11, hB[q]);
                }
            }
            #pragma unroll
            for (int q = 0; q < 8; q++) {
                float a, b;
                upk2(hA[q], a, b); F2 p0 = pk2(fmaxf(a, 0.f), fmaxf(b, 0.f));
                upk2(hB[q], a, b); F2 p1 = pk2(fmaxf(a, 0.f), fmaxf(b, 0.f));
                ulonglong2 st; st.x = p0; st.y = p1;
                *(ulonglong2*)&h2S[q * 64 + 2 * l] = st;
            }
        }
        __syncwarp();

        // --- heads: 64 -> 30, lane owns c = l (weights in registers) ---
        {
            F2 hd[8];
            #pragma unroll
            for (int q = 0; q < 8; q++) hd[q] = HBd;
            #pragma unroll 2
            for (int jj = 0; jj < 32; jj++) {
                const int j = jj * 2;
                F2 w0 = dup2(HWreg[j]);
                F2 w1 = dup2(HWreg[j + 1]);
                #pragma unroll
                for (int q = 0; q < 8; q++) {
                    ulonglong2 v = *(const ulonglong2*)&h2S[q * 64 + j];
                    hd[q] = fma2(v.x, w0, hd[q]);
                    hd[q] = fma2(v.y, w1, hd[q]);
                }
            }
            #pragma unroll
            for (int q = 0; q < 8; q++) hdS[q * 32 + l] = hd[q];
        }
        __syncwarp();

        // ===== mixture: step p, 16 quad-seqs, 2 lanes/seq =====
        {
            const float xt_m = xSf[(p + 1) * 16 + r_m];
            float ck[5], ak[5];
            float cmax = -1e30f, amax = -1e30f;
            #pragma unroll
            for (int k = 0; k < 5; k++) {
                float mu = hdf[hd_base + (kb_m + k) * 2];
                float sg = hdf[hd_base + (10 + kb_m + k) * 2];
                float al = hdf[hd_base + (20 + kb_m + k) * 2];
                float z = (xt_m - mu) * __expf(-sg);
                float cc = fmaf(z, -0.5f * z, al - sg) - HALF_LOG2PI;
                ck[k] = cc; ak[k] = al;
                cmax = fmaxf(cmax, cc); amax = fmaxf(amax, al);
            }
            cmax = fmaxf(cmax, __shfl_xor_sync(FULL, cmax, 1));
            amax = fmaxf(amax, __shfl_xor_sync(FULL, amax, 1));
            float sc = 0.0f, sa = 0.0f;
            #pragma unroll
            for (int k = 0; k < 5; k++) {
                sc += __expf(ck[k] - cmax);
                sa += __expf(ak[k] - amax);
            }
            sc += __shfl_xor_sync(FULL, sc, 1);
            sa += __shfl_xor_sync(FULL, sa, 1);
            res += (cmax + __logf(sc)) - (amax + __logf(sa));
        }
    }

    // ---- final cross-warp reduction ----
    if ((l & 1) == 0) sm[OFF_RES + (quad * 4 + p) * 16 + (l >> 1)] = res;
    __syncthreads();
    if (tid < 32) {
        int qd = tid >> 4, sq = tid & 15;
        const float* rb = sm + OFF_RES + qd * 64;
        out[blockIdx.x * 32 + qd * 16 + sq] =
            expf(rb[0 * 16 + sq] + rb[1 * 16 + sq] + rb[2 * 16 + sq] + rb[3 * 16 + sq]);
    }
}

extern "C" void kernel_launch(void* const* d_in, const int* in_sizes, int n_in,
                              void* d_out, int out_size) {
    const float* x      = (const float*)d_in[0];
    const float* enc1_w = (const float*)d_in[1];
    const float* enc1_b = (const float*)d_in[2];
    const float* enc2_w = (const float*)d_in[3];
    const float* enc2_b = (const float*)d_in[4];
    const float* A      = (const float*)d_in[5];
    const float* init_w = (const float*)d_in[6];
    const float* n1w    = (const float*)d_in[7];
    const float* n1b    = (const float*)d_in[8];
    const float* n2w    = (const float*)d_in[9];
    const float* n2b    = (const float*)d_in[10];
    const float* mu_w   = (const float*)d_in[11];
    const float* mu_b   = (const float*)d_in[12];
    const float* sg_w   = (const float*)d_in[13];
    const float* sg_b   = (const float*)d_in[14];
    const float* al_w   = (const float*)d_in[15];
    const float* al_b   = (const float*)d_in[16];
    float* out = (float*)d_out;

    const int smem_bytes = SMEM_FLOATS * (int)sizeof(float);
    cudaFuncSetAttribute(wfa_kernel, cudaFuncAttributeMaxDynamicSharedMemorySize, smem_bytes);
    wfa_kernel<<<NBLOCKS, THREADS, smem_bytes>>>(
        x, enc1_w, enc1_b, enc2_w, enc2_b, A, init_w,
        n1w, n1b, n2w, n2b, mu_w, mu_b, sg_w, sg_b, al_w, al_b, out);
}